// round 2
// baseline (speedup 1.0000x reference)
#include <cuda_runtime.h>
#include <cuda_bf16.h>

#define BATCH 64
#define CH    256
#define FH    100
#define FW    152
#define RES7  7
#define KDIM  12544      // CH * 49
#define NOUT  1024
#define KSPLIT 37
#define NCHUNKS 784      // KDIM / 16

// scratch (no allocations allowed)
__device__ float g_feat[BATCH * KDIM];                 // pooled features [m][k]
__device__ float g_part[(size_t)KSPLIT * NOUT * BATCH]; // GEMM partials [split][n][m]

// ---------------------------------------------------------------------------
// Kernel 1: RoIAlign (torchvision-style, aligned=False, SR=2, SCALE=1/16)
// One thread per output element (b, c, py, px); 4 bilinear samples each.
// ---------------------------------------------------------------------------
__global__ void roi_kernel(const float* __restrict__ x, const float* __restrict__ bbox) {
    int idx = blockIdx.x * blockDim.x + threadIdx.x;
    if (idx >= BATCH * CH * RES7 * RES7) return;

    int p  = idx % 49;
    int c  = (idx / 49) % CH;
    int b  = idx / (49 * CH);
    int py = p / 7;
    int px = p % 7;

    // bbox row: [xa, xb, ya, yb]; reference permutes to x1=xa, y1=ya, x2=xb, y2=yb
    float x1 = __ldg(&bbox[b * 4 + 0]) * 0.0625f;
    float x2 = __ldg(&bbox[b * 4 + 1]) * 0.0625f;
    float y1 = __ldg(&bbox[b * 4 + 2]) * 0.0625f;
    float y2 = __ldg(&bbox[b * 4 + 3]) * 0.0625f;

    float roi_w = fmaxf(x2 - x1, 1.0f);
    float roi_h = fmaxf(y2 - y1, 1.0f);
    float bin_w = roi_w * (1.0f / 7.0f);
    float bin_h = roi_h * (1.0f / 7.0f);

    const float* f = x + ((size_t)b * CH + c) * (FH * FW);

    float sum = 0.0f;
    #pragma unroll
    for (int sy = 0; sy < 2; ++sy) {
        // grid[2*py+sy] = py + (sy + 0.5)/2
        float gy = (float)py + ((float)sy + 0.5f) * 0.5f;
        float yy = y1 + gy * bin_h;
        bool  vy = (yy >= -1.0f) && (yy <= (float)FH);
        float ycf = fminf(fmaxf(yy, 0.0f), (float)(FH - 1));
        int   y0  = (int)floorf(ycf);
        if (y0 > FH - 1) y0 = FH - 1;
        int   y1i = min(y0 + 1, FH - 1);
        float ly  = ycf - (float)y0;
        float hy  = 1.0f - ly;
        #pragma unroll
        for (int sx = 0; sx < 2; ++sx) {
            float gx = (float)px + ((float)sx + 0.5f) * 0.5f;
            float xx = x1 + gx * bin_w;
            bool  vx = (xx >= -1.0f) && (xx <= (float)FW);
            float xcf = fminf(fmaxf(xx, 0.0f), (float)(FW - 1));
            int   x0  = (int)floorf(xcf);
            if (x0 > FW - 1) x0 = FW - 1;
            int   x1i = min(x0 + 1, FW - 1);
            float lx  = xcf - (float)x0;
            float hx  = 1.0f - lx;
            if (vy && vx) {
                float v00 = f[y0  * FW + x0 ];
                float v01 = f[y0  * FW + x1i];
                float v10 = f[y1i * FW + x0 ];
                float v11 = f[y1i * FW + x1i];
                sum += hy * (hx * v00 + lx * v01) + ly * (hx * v10 + lx * v11);
            }
        }
    }
    g_feat[idx] = sum * 0.25f;   // idx == b*KDIM + c*49 + p
}

// ---------------------------------------------------------------------------
// Kernel 2: fp32 GEMM partials: part[s][n][m] = sum_{k in split s} feat[m][k]*W[n][k]
// Block tile 64m x 64n, BK=16, 128 threads, 8x4 micro-tile per thread.
// Grid (16 n-tiles, 37 k-splits) = 592 blocks = exactly 4 per SM.
// ---------------------------------------------------------------------------
__global__ void __launch_bounds__(128) gemm_kernel(const float* __restrict__ Wt) {
    __shared__ float As[16][64];   // [k][m]
    __shared__ float Bs[16][64];   // [k][n]

    const int n0 = blockIdx.x * 64;
    const int sy = blockIdx.y;
    const int c0 = (sy * NCHUNKS) / KSPLIT;
    const int c1 = ((sy + 1) * NCHUNKS) / KSPLIT;

    const int tid  = threadIdx.x;
    const int rowi = tid >> 4;     // 0..7  -> m base = rowi*8
    const int coli = tid & 15;     // 0..15 -> n base = coli*4

    float acc[8][4];
    #pragma unroll
    for (int i = 0; i < 8; ++i)
        #pragma unroll
        for (int j = 0; j < 4; ++j) acc[i][j] = 0.0f;

    const int lm = tid >> 2;          // 0..31
    const int lk = (tid & 3) * 4;     // 0,4,8,12

    for (int cc = c0; cc < c1; ++cc) {
        const int kc = cc * 16;
        #pragma unroll
        for (int it = 0; it < 2; ++it) {
            int m = lm + it * 32;
            float4 fa = *(const float4*)(g_feat + (size_t)m * KDIM + kc + lk);
            float4 fb = *(const float4*)(Wt + (size_t)(n0 + m) * KDIM + kc + lk);
            As[lk + 0][m] = fa.x; As[lk + 1][m] = fa.y;
            As[lk + 2][m] = fa.z; As[lk + 3][m] = fa.w;
            Bs[lk + 0][m] = fb.x; Bs[lk + 1][m] = fb.y;
            Bs[lk + 2][m] = fb.z; Bs[lk + 3][m] = fb.w;
        }
        __syncthreads();
        #pragma unroll
        for (int kk = 0; kk < 16; ++kk) {
            float a[8], bv[4];
            *(float4*)&a[0] = *(const float4*)&As[kk][rowi * 8];
            *(float4*)&a[4] = *(const float4*)&As[kk][rowi * 8 + 4];
            *(float4*)&bv[0] = *(const float4*)&Bs[kk][coli * 4];
            #pragma unroll
            for (int i = 0; i < 8; ++i)
                #pragma unroll
                for (int j = 0; j < 4; ++j)
                    acc[i][j] = fmaf(a[i], bv[j], acc[i][j]);
        }
        __syncthreads();
    }

    #pragma unroll
    for (int j = 0; j < 4; ++j) {
        int n = n0 + coli * 4 + j;
        float* pp = g_part + ((size_t)sy * NOUT + n) * BATCH + rowi * 8;
        float4 lo = make_float4(acc[0][j], acc[1][j], acc[2][j], acc[3][j]);
        float4 hi = make_float4(acc[4][j], acc[5][j], acc[6][j], acc[7][j]);
        *(float4*)pp = lo;
        *(float4*)(pp + 4) = hi;
    }
}

// ---------------------------------------------------------------------------
// Kernel 3: reduce partials + bias + ReLU + batch-norm over the 64-row batch.
// One block per output column n; 64 threads (one per row m).
// ---------------------------------------------------------------------------
__global__ void bn_kernel(const float* __restrict__ fc_b,
                          const float* __restrict__ gamma,
                          const float* __restrict__ beta,
                          float* __restrict__ out) {
    const int n = blockIdx.x;
    const int m = threadIdx.x;   // 0..63

    float s = 0.0f;
    #pragma unroll 4
    for (int sp = 0; sp < KSPLIT; ++sp)
        s += g_part[((size_t)sp * NOUT + n) * BATCH + m];

    float h = fmaxf(s + __ldg(&fc_b[n]), 0.0f);

    float v1 = h, v2 = h * h;
    #pragma unroll
    for (int o = 16; o > 0; o >>= 1) {
        v1 += __shfl_down_sync(0xffffffffu, v1, o);
        v2 += __shfl_down_sync(0xffffffffu, v2, o);
    }
    __shared__ float s1[2], s2[2];
    int wid = m >> 5, lid = m & 31;
    if (lid == 0) { s1[wid] = v1; s2[wid] = v2; }
    __syncthreads();
    float t1 = s1[0] + s1[1];
    float t2 = s2[0] + s2[1];
    float mu  = t1 * (1.0f / 64.0f);
    float var = t2 * (1.0f / 64.0f) - mu * mu;
    float inv = rsqrtf(var + 1e-5f);
    out[(size_t)m * NOUT + n] = (h - mu) * inv * __ldg(&gamma[n]) + __ldg(&beta[n]);
}

// ---------------------------------------------------------------------------
extern "C" void kernel_launch(void* const* d_in, const int* in_sizes, int n_in,
                              void* d_out, int out_size) {
    const float* x     = (const float*)d_in[0];   // [64,256,100,152]
    const float* bbox  = (const float*)d_in[1];   // [64,4] = [xa,xb,ya,yb]
    const float* fc_w  = (const float*)d_in[2];   // [1024,12544]
    const float* fc_b  = (const float*)d_in[3];   // [1024]
    const float* gamma = (const float*)d_in[4];   // [1024]
    const float* beta  = (const float*)d_in[5];   // [1024]
    float* out = (float*)d_out;                   // [64,1024]

    roi_kernel<<<(BATCH * CH * 49 + 255) / 256, 256>>>(x, bbox);
    gemm_kernel<<<dim3(NOUT / 64, KSPLIT), 128>>>(fc_w);
    bn_kernel<<<NOUT, BATCH>>>(fc_b, gamma, beta, out);
}

// round 5
// speedup vs baseline: 1.6684x; 1.6684x over previous
#include <cuda_runtime.h>
#include <cuda_bf16.h>
#include <cstdint>

#define BATCH 64
#define CH    256
#define FH    100
#define FW    152
#define KDIM  12544      // CH * 49
#define NOUT  1024
#define KSPLIT 37
#define NCHUNKS 784      // KDIM / 16 (BK=16 chunks)

// scratch (no allocations allowed)
__device__ float g_feat[BATCH * KDIM];                  // pooled features [m][k]
__device__ float g_part[(size_t)KSPLIT * NOUT * BATCH]; // GEMM partials [split][n][m]

// ---------------------------------------------------------------------------
// Kernel 1: RoIAlign (torchvision-style, aligned=False, SR=2, SCALE=1/16)
// ---------------------------------------------------------------------------
__global__ void roi_kernel(const float* __restrict__ x, const float* __restrict__ bbox) {
    int idx = blockIdx.x * blockDim.x + threadIdx.x;
    if (idx >= BATCH * CH * 49) return;

    int p  = idx % 49;
    int c  = (idx / 49) % CH;
    int b  = idx / (49 * CH);
    int py = p / 7;
    int px = p % 7;

    float x1 = __ldg(&bbox[b * 4 + 0]) * 0.0625f;
    float x2 = __ldg(&bbox[b * 4 + 1]) * 0.0625f;
    float y1 = __ldg(&bbox[b * 4 + 2]) * 0.0625f;
    float y2 = __ldg(&bbox[b * 4 + 3]) * 0.0625f;

    float bin_w = fmaxf(x2 - x1, 1.0f) * (1.0f / 7.0f);
    float bin_h = fmaxf(y2 - y1, 1.0f) * (1.0f / 7.0f);

    const float* f = x + ((size_t)b * CH + c) * (FH * FW);

    float sum = 0.0f;
    #pragma unroll
    for (int sy = 0; sy < 2; ++sy) {
        float gy = (float)py + ((float)sy + 0.5f) * 0.5f;
        float yy = y1 + gy * bin_h;
        bool  vy = (yy >= -1.0f) && (yy <= (float)FH);
        float ycf = fminf(fmaxf(yy, 0.0f), (float)(FH - 1));
        int   y0  = (int)floorf(ycf);
        int   y1i = min(y0 + 1, FH - 1);
        float ly  = ycf - (float)y0;
        float hy  = 1.0f - ly;
        #pragma unroll
        for (int sx = 0; sx < 2; ++sx) {
            float gx = (float)px + ((float)sx + 0.5f) * 0.5f;
            float xx = x1 + gx * bin_w;
            bool  vx = (xx >= -1.0f) && (xx <= (float)FW);
            float xcf = fminf(fmaxf(xx, 0.0f), (float)(FW - 1));
            int   x0  = (int)floorf(xcf);
            int   x1i = min(x0 + 1, FW - 1);
            float lx  = xcf - (float)x0;
            float hx  = 1.0f - lx;
            if (vy && vx) {
                float v00 = __ldg(f + y0  * FW + x0 );
                float v01 = __ldg(f + y0  * FW + x1i);
                float v10 = __ldg(f + y1i * FW + x0 );
                float v11 = __ldg(f + y1i * FW + x1i);
                sum += hy * (hx * v00 + lx * v01) + ly * (hx * v10 + lx * v11);
            }
        }
    }
    g_feat[idx] = sum * 0.25f;
}

// ---------------------------------------------------------------------------
// Kernel 2: tf32 tensor-core GEMM partials.
// part[s][n][m] = sum_{k in split s} feat[m][k] * W[n][k]
// Block: 256 threads (8 warps, 2x4), tile M=64 x N=128, BK=16.
// Warp tile 32x32 = 2x4 fragments of mma.m16n8k8.
// Grid (8 n-tiles, 37 k-splits) = 296 blocks = 2 per SM.
// ---------------------------------------------------------------------------
__device__ __forceinline__ uint32_t f2tf32(float f) {
    uint32_t o;
    asm volatile("cvt.rna.tf32.f32 %0, %1;" : "=r"(o) : "f"(f));
    return o;
}

__device__ __forceinline__ void mma1688(float c[4], const uint32_t a[4], const uint32_t b[2]) {
    asm volatile(
        "mma.sync.aligned.m16n8k8.row.col.f32.tf32.tf32.f32 "
        "{%0,%1,%2,%3}, {%4,%5,%6,%7}, {%8,%9}, {%0,%1,%2,%3};"
        : "+f"(c[0]), "+f"(c[1]), "+f"(c[2]), "+f"(c[3])
        : "r"(a[0]), "r"(a[1]), "r"(a[2]), "r"(a[3]), "r"(b[0]), "r"(b[1]));
}

#define STA 20   // padded k-stride (words): (20*m + k) mod 32 covers all banks

__global__ void __launch_bounds__(256) gemm_kernel(const float* __restrict__ Wt) {
    __shared__ uint32_t As[64][STA];    // [m][k], tf32 bits
    __shared__ uint32_t Bs[128][STA];   // [n][k], tf32 bits

    const int n0 = blockIdx.x * 128;
    const int sy = blockIdx.y;
    const int c0 = (sy * NCHUNKS) / KSPLIT;
    const int c1 = ((sy + 1) * NCHUNKS) / KSPLIT;

    const int tid    = threadIdx.x;
    const int lane   = tid & 31;
    const int wid    = tid >> 5;
    const int warp_m = (wid & 1) * 32;
    const int warp_n = (wid >> 1) * 32;

    // staging indices
    const int am = tid >> 2;              // 0..63
    const int ak = (tid & 3) * 4;         // 0,4,8,12

    float acc[2][4][4];
    #pragma unroll
    for (int mi = 0; mi < 2; ++mi)
        #pragma unroll
        for (int ni = 0; ni < 4; ++ni)
            #pragma unroll
            for (int r = 0; r < 4; ++r) acc[mi][ni][r] = 0.0f;

    // prefetch first chunk into registers
    float4 fa, fb0, fb1;
    {
        const int kc = c0 * 16;
        fa  = *(const float4*)(g_feat + (size_t)am * KDIM + kc + ak);
        int l0 = tid, l1 = tid + 256;
        fb0 = *(const float4*)(Wt + (size_t)(n0 + (l0 >> 2)) * KDIM + kc + (l0 & 3) * 4);
        fb1 = *(const float4*)(Wt + (size_t)(n0 + (l1 >> 2)) * KDIM + kc + (l1 & 3) * 4);
    }

    for (int cc = c0; cc < c1; ++cc) {
        // stage current registers -> smem (with tf32 conversion)
        As[am][ak + 0] = f2tf32(fa.x); As[am][ak + 1] = f2tf32(fa.y);
        As[am][ak + 2] = f2tf32(fa.z); As[am][ak + 3] = f2tf32(fa.w);
        {
            int l0 = tid, l1 = tid + 256;
            int bn0 = l0 >> 2, bk0 = (l0 & 3) * 4;
            int bn1 = l1 >> 2, bk1 = (l1 & 3) * 4;
            Bs[bn0][bk0 + 0] = f2tf32(fb0.x); Bs[bn0][bk0 + 1] = f2tf32(fb0.y);
            Bs[bn0][bk0 + 2] = f2tf32(fb0.z); Bs[bn0][bk0 + 3] = f2tf32(fb0.w);
            Bs[bn1][bk1 + 0] = f2tf32(fb1.x); Bs[bn1][bk1 + 1] = f2tf32(fb1.y);
            Bs[bn1][bk1 + 2] = f2tf32(fb1.z); Bs[bn1][bk1 + 3] = f2tf32(fb1.w);
        }
        __syncthreads();

        // prefetch next chunk (overlaps with MMA below)
        if (cc + 1 < c1) {
            const int kc = (cc + 1) * 16;
            fa  = *(const float4*)(g_feat + (size_t)am * KDIM + kc + ak);
            int l0 = tid, l1 = tid + 256;
            fb0 = *(const float4*)(Wt + (size_t)(n0 + (l0 >> 2)) * KDIM + kc + (l0 & 3) * 4);
            fb1 = *(const float4*)(Wt + (size_t)(n0 + (l1 >> 2)) * KDIM + kc + (l1 & 3) * 4);
        }

        // compute: 2 k8-steps x (2 m-frags x 4 n-frags) MMAs
        #pragma unroll
        for (int kk = 0; kk < 2; ++kk) {
            const int kb = kk * 8;
            uint32_t a[2][4], b[4][2];
            #pragma unroll
            for (int mi = 0; mi < 2; ++mi) {
                int m = warp_m + mi * 16 + (lane >> 2);
                int k = kb + (lane & 3);
                a[mi][0] = As[m][k];
                a[mi][1] = As[m + 8][k];
                a[mi][2] = As[m][k + 4];
                a[mi][3] = As[m + 8][k + 4];
            }
            #pragma unroll
            for (int ni = 0; ni < 4; ++ni) {
                int n = warp_n + ni * 8 + (lane >> 2);
                int k = kb + (lane & 3);
                b[ni][0] = Bs[n][k];
                b[ni][1] = Bs[n][k + 4];
            }
            #pragma unroll
            for (int mi = 0; mi < 2; ++mi)
                #pragma unroll
                for (int ni = 0; ni < 4; ++ni)
                    mma1688(acc[mi][ni], a[mi], b[ni]);
        }
        __syncthreads();
    }

    // epilogue: scatter fragments to g_part[sy][n][m]
    #pragma unroll
    for (int mi = 0; mi < 2; ++mi) {
        #pragma unroll
        for (int ni = 0; ni < 4; ++ni) {
            int mr = warp_m + mi * 16 + (lane >> 2);
            int nc = n0 + warp_n + ni * 8 + 2 * (lane & 3);
            float* base = g_part + ((size_t)sy * NOUT + nc) * BATCH + mr;
            base[0]          = acc[mi][ni][0];
            base[BATCH]      = acc[mi][ni][1];
            base[8]          = acc[mi][ni][2];
            base[BATCH + 8]  = acc[mi][ni][3];
        }
    }
}

// ---------------------------------------------------------------------------
// Kernel 3: reduce partials + bias + ReLU + batch-norm over the 64-row batch.
// ---------------------------------------------------------------------------
__global__ void bn_kernel(const float* __restrict__ fc_b,
                          const float* __restrict__ gamma,
                          const float* __restrict__ beta,
                          float* __restrict__ out) {
    const int n = blockIdx.x;
    const int m = threadIdx.x;   // 0..63

    float s = 0.0f;
    #pragma unroll 4
    for (int sp = 0; sp < KSPLIT; ++sp)
        s += g_part[((size_t)sp * NOUT + n) * BATCH + m];

    float h = fmaxf(s + __ldg(&fc_b[n]), 0.0f);

    float v1 = h, v2 = h * h;
    #pragma unroll
    for (int o = 16; o > 0; o >>= 1) {
        v1 += __shfl_down_sync(0xffffffffu, v1, o);
        v2 += __shfl_down_sync(0xffffffffu, v2, o);
    }
    __shared__ float s1[2], s2[2];
    int wid = m >> 5, lid = m & 31;
    if (lid == 0) { s1[wid] = v1; s2[wid] = v2; }
    __syncthreads();
    float t1 = s1[0] + s1[1];
    float t2 = s2[0] + s2[1];
    float mu  = t1 * (1.0f / 64.0f);
    float var = t2 * (1.0f / 64.0f) - mu * mu;
    float inv = rsqrtf(var + 1e-5f);
    out[(size_t)m * NOUT + n] = (h - mu) * inv * __ldg(&gamma[n]) + __ldg(&beta[n]);
}

// ---------------------------------------------------------------------------
extern "C" void kernel_launch(void* const* d_in, const int* in_sizes, int n_in,
                              void* d_out, int out_size) {
    const float* x     = (const float*)d_in[0];   // [64,256,100,152]
    const float* bbox  = (const float*)d_in[1];   // [64,4] = [xa,xb,ya,yb]
    const float* fc_w  = (const float*)d_in[2];   // [1024,12544]
    const float* fc_b  = (const float*)d_in[3];   // [1024]
    const float* gamma = (const float*)d_in[4];   // [1024]
    const float* beta  = (const float*)d_in[5];   // [1024]
    float* out = (float*)d_out;                   // [64,1024]

    roi_kernel<<<(BATCH * CH * 49 + 255) / 256, 256>>>(x, bbox);
    gemm_kernel<<<dim3(NOUT / 128, KSPLIT), 256>>>(fc_w);
    bn_kernel<<<NOUT, BATCH>>>(fc_b, gamma, beta, out);
}